// round 3
// baseline (speedup 1.0000x reference)
#include <cuda_runtime.h>
#include <cuda_bf16.h>
#include <math.h>

// ---------------- problem constants ----------------
// L0: 512000 -> 102400, E=1024000, 100 -> 256, relu
// L1: 102400 -> 10240,  E=102400,  256 -> 256, relu
// L2: 10240  -> 1024,   E=10240,   256 -> 47,  log_softmax

#define ND_MAX 102400
#define E_MAX  1024000

// ---------------- scratch (__device__ globals; no allocation allowed) ------
__device__ int   g_cnt[ND_MAX];
__device__ int   g_off[ND_MAX];
__device__ int   g_cur[ND_MAX];
__device__ int   g_esrc[E_MAX];
__device__ float g_mean[102400 * 100];          // L0: 102400x100; L1: 10240x256; L2: 1024x256
__device__ float g_h1[(size_t)102400 * 256];
__device__ float g_h2[10240 * 256];
__device__ float g_logits[1024 * 47];

// ---------------- small utility kernels ----------------
__global__ void zero_i_k(int* p, int n) {
    int i = blockIdx.x * blockDim.x + threadIdx.x;
    if (i < n) p[i] = 0;
}

__global__ void hist_k(const int* __restrict__ dst, int ne, int* __restrict__ cnt) {
    int i = blockIdx.x * blockDim.x + threadIdx.x;
    if (i < ne) atomicAdd(&cnt[dst[i]], 1);
}

// single-block exclusive scan over cnt -> off (and cur copy). n <= 102400.
__global__ void scan_k(const int* __restrict__ cnt, int* __restrict__ off,
                       int* __restrict__ cur, int n) {
    __shared__ int sh[1024];
    __shared__ int running_sh;
    if (threadIdx.x == 0) running_sh = 0;
    __syncthreads();
    for (int base = 0; base < n; base += 1024) {
        int i = base + (int)threadIdx.x;
        int v = (i < n) ? cnt[i] : 0;
        sh[threadIdx.x] = v;
        __syncthreads();
        #pragma unroll
        for (int s = 1; s < 1024; s <<= 1) {
            int t = (threadIdx.x >= (unsigned)s) ? sh[threadIdx.x - s] : 0;
            __syncthreads();
            sh[threadIdx.x] += t;
            __syncthreads();
        }
        int running = running_sh;
        int excl = sh[threadIdx.x] - v + running;
        if (i < n) { off[i] = excl; cur[i] = excl; }
        __syncthreads();
        if (threadIdx.x == 1023) running_sh = running + sh[1023];
        __syncthreads();
    }
}

__global__ void scatter_k(const int* __restrict__ src, const int* __restrict__ dst,
                          int ne, int* __restrict__ cur, int* __restrict__ esrc) {
    int i = blockIdx.x * blockDim.x + threadIdx.x;
    if (i < ne) {
        int p = atomicAdd(&cur[dst[i]], 1);
        esrc[p] = src[i];
    }
}

// ---------------- mean aggregation: one warp per destination node ----------
// C must be divisible by 4. Each lane accumulates float4 chunks.
template <int C>
__global__ void gather_mean_k(const float* __restrict__ x, const int* __restrict__ esrc,
                              const int* __restrict__ off, const int* __restrict__ cnt,
                              float* __restrict__ mean, int n_dst) {
    int warp = (blockIdx.x * blockDim.x + threadIdx.x) >> 5;
    int lane = threadIdx.x & 31;
    if (warp >= n_dst) return;
    int s = off[warp];
    int c = cnt[warp];
    constexpr int C4 = C / 4;                 // float4 chunks per row
    constexpr int R = (C4 + 31) / 32;         // chunks per lane
    float4 acc[R];
    #pragma unroll
    for (int r = 0; r < R; r++) acc[r] = make_float4(0.f, 0.f, 0.f, 0.f);

    int nxt = (c > 0) ? esrc[s] : 0;
    for (int e = 0; e < c; e++) {
        int row = nxt;
        if (e + 1 < c) nxt = esrc[s + e + 1];
        const float4* xr = (const float4*)(x + (size_t)row * C);
        #pragma unroll
        for (int r = 0; r < R; r++) {
            int f = lane + 32 * r;
            if (f < C4) {
                float4 v = __ldg(&xr[f]);
                acc[r].x += v.x; acc[r].y += v.y; acc[r].z += v.z; acc[r].w += v.w;
            }
        }
    }
    float inv = 1.f / (float)(c > 1 ? c : 1);
    float4* mr = (float4*)(mean + (size_t)warp * C);
    #pragma unroll
    for (int r = 0; r < R; r++) {
        int f = lane + 32 * r;
        if (f < C4) {
            float4 v;
            v.x = acc[r].x * inv; v.y = acc[r].y * inv;
            v.z = acc[r].z * inv; v.w = acc[r].w * inv;
            mr[f] = v;
        }
    }
}

// ---------------- dual-input fp32 GEMM ----------------
// C[M,N] = A1[M,K] @ W1[N,K]^T + A2[M,K] @ W2[N,K]^T + bias ;  optional relu
#define GBM 128
#define GBN 64
#define GBK 16

__global__ __launch_bounds__(256) void gemm_dual_k(
    const float* __restrict__ A1, const float* __restrict__ W1,
    const float* __restrict__ A2, const float* __restrict__ W2,
    const float* __restrict__ bias, float* __restrict__ Cout,
    int M, int N, int K, int relu) {
    __shared__ float As[GBK][GBM + 4];
    __shared__ float Bs[GBK][GBN + 4];
    int tid = threadIdx.x;
    int tx = tid & 15;        // 16 cols of threads -> 4 outputs each (64)
    int ty = tid >> 4;        // 16 rows of threads -> 8 outputs each (128)
    int row0 = blockIdx.y * GBM;
    int col0 = blockIdx.x * GBN;

    float acc[8][4];
    #pragma unroll
    for (int i = 0; i < 8; i++)
        #pragma unroll
        for (int j = 0; j < 4; j++) acc[i][j] = 0.f;

    for (int pass = 0; pass < 2; pass++) {
        const float* A = pass ? A2 : A1;
        const float* W = pass ? W2 : W1;
        for (int k0 = 0; k0 < K; k0 += GBK) {
            #pragma unroll
            for (int l = 0; l < 8; l++) {
                int e = tid + l * 256;
                int kk = e & 15, m = e >> 4;
                int gk = k0 + kk, gm = row0 + m;
                As[kk][m] = (gk < K && gm < M) ? A[(size_t)gm * K + gk] : 0.f;
            }
            #pragma unroll
            for (int l = 0; l < 4; l++) {
                int e = tid + l * 256;
                int kk = e & 15, nn = e >> 4;
                int gk = k0 + kk, gn = col0 + nn;
                Bs[kk][nn] = (gk < K && gn < N) ? W[(size_t)gn * K + gk] : 0.f;
            }
            __syncthreads();
            #pragma unroll
            for (int kk = 0; kk < GBK; kk++) {
                float4 a0 = *(const float4*)&As[kk][ty * 8];
                float4 a1 = *(const float4*)&As[kk][ty * 8 + 4];
                float4 b0 = *(const float4*)&Bs[kk][tx * 4];
                float a[8] = {a0.x, a0.y, a0.z, a0.w, a1.x, a1.y, a1.z, a1.w};
                float b[4] = {b0.x, b0.y, b0.z, b0.w};
                #pragma unroll
                for (int i = 0; i < 8; i++)
                    #pragma unroll
                    for (int j = 0; j < 4; j++) acc[i][j] = fmaf(a[i], b[j], acc[i][j]);
            }
            __syncthreads();
        }
    }

    #pragma unroll
    for (int i = 0; i < 8; i++) {
        int r = row0 + ty * 8 + i;
        if (r >= M) continue;
        #pragma unroll
        for (int j = 0; j < 4; j++) {
            int c = col0 + tx * 4 + j;
            if (c >= N) continue;
            float v = acc[i][j] + __ldg(&bias[c]);
            if (relu) v = fmaxf(v, 0.f);
            Cout[(size_t)r * N + c] = v;
        }
    }
}

// ---------------- log-softmax: one warp per row ----------------
__global__ void logsoftmax_k(const float* __restrict__ in, float* __restrict__ out,
                             int M, int N) {
    int row = blockIdx.x * (blockDim.x >> 5) + (threadIdx.x >> 5);
    int lane = threadIdx.x & 31;
    if (row >= M) return;
    const float* r = in + (size_t)row * N;
    float m = -1e30f;
    for (int c = lane; c < N; c += 32) m = fmaxf(m, r[c]);
    #pragma unroll
    for (int s = 16; s; s >>= 1) m = fmaxf(m, __shfl_xor_sync(0xffffffffu, m, s));
    float sum = 0.f;
    for (int c = lane; c < N; c += 32) sum += expf(r[c] - m);
    #pragma unroll
    for (int s = 16; s; s >>= 1) sum += __shfl_xor_sync(0xffffffffu, sum, s);
    float lse = logf(sum) + m;
    for (int c = lane; c < N; c += 32) out[(size_t)row * N + c] = r[c] - lse;
}

// ---------------- host driver ----------------
static void build_csr(const int* src, const int* dst, int ne, int nd,
                      int* cnt, int* off, int* cur, int* esrc) {
    zero_i_k<<<(nd + 255) / 256, 256>>>(cnt, nd);
    hist_k<<<(ne + 255) / 256, 256>>>(dst, ne, cnt);
    scan_k<<<1, 1024>>>(cnt, off, cur, nd);
    scatter_k<<<(ne + 255) / 256, 256>>>(src, dst, ne, cur, esrc);
}

extern "C" void kernel_launch(void* const* d_in, const int* in_sizes, int n_in,
                              void* d_out, int out_size) {
    const float* x    = (const float*)d_in[0];
    const int*   src0 = (const int*)d_in[1];
    const int*   dst0 = (const int*)d_in[2];
    const int*   src1 = (const int*)d_in[3];
    const int*   dst1 = (const int*)d_in[4];
    const int*   src2 = (const int*)d_in[5];
    const int*   dst2 = (const int*)d_in[6];
    const float* Wl0 = (const float*)d_in[7];
    const float* bl0 = (const float*)d_in[8];
    const float* Wr0 = (const float*)d_in[9];
    const float* Wl1 = (const float*)d_in[10];
    const float* bl1 = (const float*)d_in[11];
    const float* Wr1 = (const float*)d_in[12];
    const float* Wl2 = (const float*)d_in[13];
    const float* bl2 = (const float*)d_in[14];
    const float* Wr2 = (const float*)d_in[15];
    float* out = (float*)d_out;

    int *cnt, *off, *cur, *esrc;
    float *mean, *h1, *h2, *logits;
    cudaGetSymbolAddress((void**)&cnt, g_cnt);
    cudaGetSymbolAddress((void**)&off, g_off);
    cudaGetSymbolAddress((void**)&cur, g_cur);
    cudaGetSymbolAddress((void**)&esrc, g_esrc);
    cudaGetSymbolAddress((void**)&mean, g_mean);
    cudaGetSymbolAddress((void**)&h1, g_h1);
    cudaGetSymbolAddress((void**)&h2, g_h2);
    cudaGetSymbolAddress((void**)&logits, g_logits);

    // ---------- layer 0 : x[512000,100] -> h1[102400,256], relu ----------
    build_csr(src0, dst0, 1024000, 102400, cnt, off, cur, esrc);
    gather_mean_k<100><<<(102400 * 32 + 255) / 256, 256>>>(x, esrc, off, cnt, mean, 102400);
    {
        dim3 g((256 + GBN - 1) / GBN, (102400 + GBM - 1) / GBM);
        gemm_dual_k<<<g, 256>>>(mean, Wl0, x, Wr0, bl0, h1, 102400, 256, 100, 1);
    }

    // ---------- layer 1 : h1[102400,256] -> h2[10240,256], relu ----------
    build_csr(src1, dst1, 102400, 10240, cnt, off, cur, esrc);
    gather_mean_k<256><<<(10240 * 32 + 255) / 256, 256>>>(h1, esrc, off, cnt, mean, 10240);
    {
        dim3 g((256 + GBN - 1) / GBN, (10240 + GBM - 1) / GBM);
        gemm_dual_k<<<g, 256>>>(mean, Wl1, h1, Wr1, bl1, h2, 10240, 256, 256, 1);
    }

    // ---------- layer 2 : h2[10240,256] -> logits[1024,47] ----------
    build_csr(src2, dst2, 10240, 1024, cnt, off, cur, esrc);
    gather_mean_k<256><<<(1024 * 32 + 255) / 256, 256>>>(h2, esrc, off, cnt, mean, 1024);
    {
        dim3 g((47 + GBN - 1) / GBN, (1024 + GBM - 1) / GBM);
        gemm_dual_k<<<g, 256>>>(mean, Wl2, h2, Wr2, bl2, logits, 1024, 47, 256, 0);
    }

    // ---------- log_softmax ----------
    logsoftmax_k<<<(1024 + 7) / 8, 256>>>(logits, out, 1024, 47);
}

// round 4
// speedup vs baseline: 1.5495x; 1.5495x over previous
#include <cuda_runtime.h>
#include <cuda_bf16.h>
#include <math.h>

// ---------------- problem constants ----------------
// L0: 512000 -> 102400, E=1024000, 100 -> 256, relu
// L1: 102400 -> 10240,  E=102400,  256 -> 256, relu
// L2: 10240  -> 1024,   E=10240,   256 -> 47,  log_softmax

#define ND_MAX 102400
#define E_MAX  1024000

// ---------------- scratch (__device__ globals; no allocation allowed) ------
__device__ int   g_cnt[ND_MAX];
__device__ int   g_off[ND_MAX];
__device__ int   g_cur[ND_MAX];
__device__ int   g_esrc[E_MAX];
__device__ float g_mean[102400 * 100];          // L0: 102400x100; L1: 10240x256; L2: 1024x256
__device__ float g_h1[(size_t)102400 * 256];
__device__ float g_h2[10240 * 256];
__device__ float g_logits[1024 * 47];

// ---------------- small utility kernels ----------------
__global__ void zero_i_k(int* p, int n) {
    int i = blockIdx.x * blockDim.x + threadIdx.x;
    if (i < n) p[i] = 0;
}

__global__ void hist_k(const int* __restrict__ dst, int ne, int* __restrict__ cnt) {
    int i = blockIdx.x * blockDim.x + threadIdx.x;
    if (i < ne) atomicAdd(&cnt[dst[i]], 1);
}

// single-block exclusive scan over cnt -> off (and cur copy). n <= 102400.
// two-level shfl scan per 1024-tile; serial running offset across tiles.
__global__ void scan_k(const int* __restrict__ cnt, int* __restrict__ off,
                       int* __restrict__ cur, int n) {
    __shared__ int wsum[32];
    __shared__ int running_sh;
    int tid = threadIdx.x;
    int lane = tid & 31, wid = tid >> 5;
    if (tid == 0) running_sh = 0;
    __syncthreads();
    for (int base = 0; base < n; base += 1024) {
        int i = base + tid;
        int v = (i < n) ? cnt[i] : 0;
        int s = v;
        #pragma unroll
        for (int d = 1; d < 32; d <<= 1) {
            int t = __shfl_up_sync(0xffffffffu, s, d);
            if (lane >= d) s += t;
        }
        if (lane == 31) wsum[wid] = s;
        __syncthreads();
        if (wid == 0) {
            int w = wsum[lane];
            #pragma unroll
            for (int d = 1; d < 32; d <<= 1) {
                int t = __shfl_up_sync(0xffffffffu, w, d);
                if (lane >= d) w += t;
            }
            wsum[lane] = w;
        }
        __syncthreads();
        int incl = s + (wid ? wsum[wid - 1] : 0) + running_sh;
        int excl = incl - v;
        if (i < n) { off[i] = excl; cur[i] = excl; }
        __syncthreads();
        if (tid == 1023) running_sh = incl;
        __syncthreads();
    }
}

__global__ void scatter_k(const int* __restrict__ src, const int* __restrict__ dst,
                          int ne, int* __restrict__ cur, int* __restrict__ esrc) {
    int i = blockIdx.x * blockDim.x + threadIdx.x;
    if (i < ne) {
        int p = atomicAdd(&cur[dst[i]], 1);
        esrc[p] = src[i];
    }
}

// ---------------- mean aggregation: one warp per destination node ----------
template <int C>
__global__ void gather_mean_k(const float* __restrict__ x, const int* __restrict__ esrc,
                              const int* __restrict__ off, const int* __restrict__ cnt,
                              float* __restrict__ mean, int n_dst) {
    int warp = (blockIdx.x * blockDim.x + threadIdx.x) >> 5;
    int lane = threadIdx.x & 31;
    if (warp >= n_dst) return;
    int s = off[warp];
    int c = cnt[warp];
    constexpr int C4 = C / 4;
    constexpr int R = (C4 + 31) / 32;
    float4 acc[R];
    #pragma unroll
    for (int r = 0; r < R; r++) acc[r] = make_float4(0.f, 0.f, 0.f, 0.f);

    int nxt = (c > 0) ? esrc[s] : 0;
    for (int e = 0; e < c; e++) {
        int row = nxt;
        if (e + 1 < c) nxt = esrc[s + e + 1];
        const float4* xr = (const float4*)(x + (size_t)row * C);
        #pragma unroll
        for (int r = 0; r < R; r++) {
            int f = lane + 32 * r;
            if (f < C4) {
                float4 v = __ldg(&xr[f]);
                acc[r].x += v.x; acc[r].y += v.y; acc[r].z += v.z; acc[r].w += v.w;
            }
        }
    }
    float inv = 1.f / (float)(c > 1 ? c : 1);
    float4* mr = (float4*)(mean + (size_t)warp * C);
    #pragma unroll
    for (int r = 0; r < R; r++) {
        int f = lane + 32 * r;
        if (f < C4) {
            float4 v;
            v.x = acc[r].x * inv; v.y = acc[r].y * inv;
            v.z = acc[r].z * inv; v.w = acc[r].w * inv;
            mr[f] = v;
        }
    }
}

// ---------------- TF32 tensor-core dual GEMM ----------------
// C[M,N] = A1[M,K] @ W1[N,K]^T + A2[M,K] @ W2[N,K]^T + bias ;  optional relu
// BM=128, BN=128, BK=32, 256 threads = 8 warps (4 m x 2 n), warp tile 32x64.
// fp32 inputs converted to tf32 with cvt.rna during smem fill (unbiased).

#define TBM 128
#define TBN 128
#define TBK 32
#define TPAD 36   // smem row pitch: 4*row+col mod 32 distinct -> conflict-free frags

__device__ __forceinline__ unsigned f2tf32(float f) {
    unsigned u;
    asm("cvt.rna.tf32.f32 %0, %1;" : "=r"(u) : "f"(f));
    return u;
}

__device__ __forceinline__ void mma_tf32(float* d, const unsigned* a, const unsigned* b) {
    asm volatile(
        "mma.sync.aligned.m16n8k8.row.col.f32.tf32.tf32.f32 "
        "{%0,%1,%2,%3}, {%4,%5,%6,%7}, {%8,%9}, {%0,%1,%2,%3};\n"
        : "+f"(d[0]), "+f"(d[1]), "+f"(d[2]), "+f"(d[3])
        : "r"(a[0]), "r"(a[1]), "r"(a[2]), "r"(a[3]), "r"(b[0]), "r"(b[1]));
}

__global__ __launch_bounds__(256) void gemm_dual_tf32_k(
    const float* __restrict__ A1, const float* __restrict__ W1,
    const float* __restrict__ A2, const float* __restrict__ W2,
    const float* __restrict__ bias, float* __restrict__ Cout,
    int M, int N, int K, int relu) {
    __shared__ unsigned As[TBM][TPAD];
    __shared__ unsigned Bs[TBN][TPAD];

    int tid = threadIdx.x;
    int lane = tid & 31;
    int wid = tid >> 5;
    int wm = wid & 3;           // 0..3  -> rows wm*32
    int wn = wid >> 2;          // 0..1  -> cols wn*64
    int g = lane >> 2;          // 0..7
    int tq = lane & 3;          // 0..3
    int blockM = blockIdx.y * TBM;
    int blockN = blockIdx.x * TBN;

    float acc[2][8][4];
    #pragma unroll
    for (int mt = 0; mt < 2; mt++)
        #pragma unroll
        for (int nt = 0; nt < 8; nt++)
            #pragma unroll
            for (int q = 0; q < 4; q++) acc[mt][nt][q] = 0.f;

    for (int pass = 0; pass < 2; pass++) {
        const float* A = pass ? A2 : A1;
        const float* W = pass ? W2 : W1;
        for (int k0 = 0; k0 < K; k0 += TBK) {
            // fill As: 128 rows x 8 float4-chunks
            #pragma unroll
            for (int it = 0; it < 4; it++) {
                int s = tid + it * 256;
                int row = s >> 3, c4 = s & 7;
                int gk = k0 + c4 * 4;
                float4 v = make_float4(0.f, 0.f, 0.f, 0.f);
                if (gk + 4 <= K)
                    v = *(const float4*)(A + (size_t)(blockM + row) * K + gk);
                uint4 u;
                u.x = f2tf32(v.x); u.y = f2tf32(v.y);
                u.z = f2tf32(v.z); u.w = f2tf32(v.w);
                *(uint4*)&As[row][c4 * 4] = u;
            }
            // fill Bs: 128 rows (n) x 8 float4-chunks (k)
            #pragma unroll
            for (int it = 0; it < 4; it++) {
                int s = tid + it * 256;
                int row = s >> 3, c4 = s & 7;
                int gk = k0 + c4 * 4;
                int gn = blockN + row;
                float4 v = make_float4(0.f, 0.f, 0.f, 0.f);
                if (gn < N && gk + 4 <= K)
                    v = *(const float4*)(W + (size_t)gn * K + gk);
                uint4 u;
                u.x = f2tf32(v.x); u.y = f2tf32(v.y);
                u.z = f2tf32(v.z); u.w = f2tf32(v.w);
                *(uint4*)&Bs[row][c4 * 4] = u;
            }
            __syncthreads();

            #pragma unroll
            for (int kk = 0; kk < TBK; kk += 8) {
                unsigned af[2][4], bf[8][2];
                #pragma unroll
                for (int mt = 0; mt < 2; mt++) {
                    int r0 = wm * 32 + mt * 16;
                    af[mt][0] = As[r0 + g][kk + tq];
                    af[mt][1] = As[r0 + g + 8][kk + tq];
                    af[mt][2] = As[r0 + g][kk + tq + 4];
                    af[mt][3] = As[r0 + g + 8][kk + tq + 4];
                }
                #pragma unroll
                for (int nt = 0; nt < 8; nt++) {
                    int c0 = wn * 64 + nt * 8;
                    bf[nt][0] = Bs[c0 + g][kk + tq];
                    bf[nt][1] = Bs[c0 + g][kk + tq + 4];
                }
                #pragma unroll
                for (int mt = 0; mt < 2; mt++)
                    #pragma unroll
                    for (int nt = 0; nt < 8; nt++)
                        mma_tf32(acc[mt][nt], af[mt], bf[nt]);
            }
            __syncthreads();
        }
    }

    // epilogue
    #pragma unroll
    for (int mt = 0; mt < 2; mt++) {
        int r0 = blockM + wm * 32 + mt * 16 + g;
        #pragma unroll
        for (int nt = 0; nt < 8; nt++) {
            int c = blockN + wn * 64 + nt * 8 + 2 * tq;
            #pragma unroll
            for (int half = 0; half < 2; half++) {
                int rr = r0 + half * 8;
                #pragma unroll
                for (int j = 0; j < 2; j++) {
                    int cc = c + j;
                    if (cc < N) {
                        float v = acc[mt][nt][half * 2 + j] + __ldg(&bias[cc]);
                        if (relu) v = fmaxf(v, 0.f);
                        Cout[(size_t)rr * N + cc] = v;
                    }
                }
            }
        }
    }
}

// ---------------- log-softmax: one warp per row ----------------
__global__ void logsoftmax_k(const float* __restrict__ in, float* __restrict__ out,
                             int M, int N) {
    int row = blockIdx.x * (blockDim.x >> 5) + (threadIdx.x >> 5);
    int lane = threadIdx.x & 31;
    if (row >= M) return;
    const float* r = in + (size_t)row * N;
    float m = -1e30f;
    for (int c = lane; c < N; c += 32) m = fmaxf(m, r[c]);
    #pragma unroll
    for (int s = 16; s; s >>= 1) m = fmaxf(m, __shfl_xor_sync(0xffffffffu, m, s));
    float sum = 0.f;
    for (int c = lane; c < N; c += 32) sum += expf(r[c] - m);
    #pragma unroll
    for (int s = 16; s; s >>= 1) sum += __shfl_xor_sync(0xffffffffu, sum, s);
    float lse = logf(sum) + m;
    for (int c = lane; c < N; c += 32) out[(size_t)row * N + c] = r[c] - lse;
}

// ---------------- host driver ----------------
static void build_csr(const int* src, const int* dst, int ne, int nd,
                      int* cnt, int* off, int* cur, int* esrc) {
    zero_i_k<<<(nd + 255) / 256, 256>>>(cnt, nd);
    hist_k<<<(ne + 255) / 256, 256>>>(dst, ne, cnt);
    scan_k<<<1, 1024>>>(cnt, off, cur, nd);
    scatter_k<<<(ne + 255) / 256, 256>>>(src, dst, ne, cur, esrc);
}

extern "C" void kernel_launch(void* const* d_in, const int* in_sizes, int n_in,
                              void* d_out, int out_size) {
    const float* x    = (const float*)d_in[0];
    const int*   src0 = (const int*)d_in[1];
    const int*   dst0 = (const int*)d_in[2];
    const int*   src1 = (const int*)d_in[3];
    const int*   dst1 = (const int*)d_in[4];
    const int*   src2 = (const int*)d_in[5];
    const int*   dst2 = (const int*)d_in[6];
    const float* Wl0 = (const float*)d_in[7];
    const float* bl0 = (const float*)d_in[8];
    const float* Wr0 = (const float*)d_in[9];
    const float* Wl1 = (const float*)d_in[10];
    const float* bl1 = (const float*)d_in[11];
    const float* Wr1 = (const float*)d_in[12];
    const float* Wl2 = (const float*)d_in[13];
    const float* bl2 = (const float*)d_in[14];
    const float* Wr2 = (const float*)d_in[15];
    float* out = (float*)d_out;

    int *cnt, *off, *cur, *esrc;
    float *mean, *h1, *h2, *logits;
    cudaGetSymbolAddress((void**)&cnt, g_cnt);
    cudaGetSymbolAddress((void**)&off, g_off);
    cudaGetSymbolAddress((void**)&cur, g_cur);
    cudaGetSymbolAddress((void**)&esrc, g_esrc);
    cudaGetSymbolAddress((void**)&mean, g_mean);
    cudaGetSymbolAddress((void**)&h1, g_h1);
    cudaGetSymbolAddress((void**)&h2, g_h2);
    cudaGetSymbolAddress((void**)&logits, g_logits);

    // ---------- layer 0 : x[512000,100] -> h1[102400,256], relu ----------
    build_csr(src0, dst0, 1024000, 102400, cnt, off, cur, esrc);
    gather_mean_k<100><<<(102400 * 32 + 255) / 256, 256>>>(x, esrc, off, cnt, mean, 102400);
    {
        dim3 g((256 + TBN - 1) / TBN, 102400 / TBM);
        gemm_dual_tf32_k<<<g, 256>>>(mean, Wl0, x, Wr0, bl0, h1, 102400, 256, 100, 1);
    }

    // ---------- layer 1 : h1[102400,256] -> h2[10240,256], relu ----------
    build_csr(src1, dst1, 102400, 10240, cnt, off, cur, esrc);
    gather_mean_k<256><<<(10240 * 32 + 255) / 256, 256>>>(h1, esrc, off, cnt, mean, 10240);
    {
        dim3 g((256 + TBN - 1) / TBN, 10240 / TBM);
        gemm_dual_tf32_k<<<g, 256>>>(mean, Wl1, h1, Wr1, bl1, h2, 10240, 256, 256, 1);
    }

    // ---------- layer 2 : h2[10240,256] -> logits[1024,47] ----------
    build_csr(src2, dst2, 10240, 1024, cnt, off, cur, esrc);
    gather_mean_k<256><<<(1024 * 32 + 255) / 256, 256>>>(h2, esrc, off, cnt, mean, 1024);
    {
        dim3 g((47 + TBN - 1) / TBN, 1024 / TBM);
        gemm_dual_tf32_k<<<g, 256>>>(mean, Wl2, h2, Wr2, bl2, logits, 1024, 47, 256, 0);
    }

    // ---------- log_softmax ----------
    logsoftmax_k<<<(1024 + 7) / 8, 256>>>(logits, out, 1024, 47);
}

// round 5
// speedup vs baseline: 1.7772x; 1.1470x over previous
#include <cuda_runtime.h>
#include <cuda_bf16.h>
#include <math.h>

// ---------------- problem constants ----------------
// L0: 512000 -> 102400, E=1024000, 100 -> 256, relu
// L1: 102400 -> 10240,  E=102400,  256 -> 256, relu
// L2: 10240  -> 1024,   E=10240,   256 -> 47,  log_softmax

#define ND_MAX 102400
#define E_MAX  1024000

// ---------------- scratch (__device__ globals; no allocation allowed) ------
__device__ int   g_cnt[ND_MAX];
__device__ int   g_off[ND_MAX];
__device__ int   g_cur[ND_MAX];
__device__ int   g_esrc[E_MAX];
__device__ float g_mean[102400 * 100];          // L0: 102400x100; L1: 10240x256; L2: 1024x256
__device__ float g_xr[102400 * 100];            // tf32-rounded copy of x[:102400]
__device__ float g_h1[(size_t)102400 * 256];
__device__ float g_h2[10240 * 256];
__device__ float g_logits[1024 * 47];

__device__ __forceinline__ unsigned f2tf32(float f) {
    unsigned u;
    asm("cvt.rna.tf32.f32 %0, %1;" : "=r"(u) : "f"(f));
    return u;
}
__device__ __forceinline__ float rtf32(float f) { return __uint_as_float(f2tf32(f)); }

// ---------------- small utility kernels ----------------
__global__ void zero_i_k(int* p, int n) {
    int i = blockIdx.x * blockDim.x + threadIdx.x;
    if (i < n) p[i] = 0;
}

__global__ void hist_k(const int* __restrict__ dst, int ne, int* __restrict__ cnt) {
    int i = blockIdx.x * blockDim.x + threadIdx.x;
    if (i < ne) atomicAdd(&cnt[dst[i]], 1);
}

// elementwise tf32-round (float4)
__global__ void round_tf32_k(const float* __restrict__ in, float* __restrict__ out, int n4) {
    int i = blockIdx.x * blockDim.x + threadIdx.x;
    if (i < n4) {
        float4 v = __ldg((const float4*)in + i);
        v.x = rtf32(v.x); v.y = rtf32(v.y); v.z = rtf32(v.z); v.w = rtf32(v.w);
        ((float4*)out)[i] = v;
    }
}

// single-block exclusive scan over cnt -> off (and cur copy). n <= 102400.
__global__ void scan_k(const int* __restrict__ cnt, int* __restrict__ off,
                       int* __restrict__ cur, int n) {
    __shared__ int wsum[32];
    __shared__ int running_sh;
    int tid = threadIdx.x;
    int lane = tid & 31, wid = tid >> 5;
    if (tid == 0) running_sh = 0;
    __syncthreads();
    for (int base = 0; base < n; base += 1024) {
        int i = base + tid;
        int v = (i < n) ? cnt[i] : 0;
        int s = v;
        #pragma unroll
        for (int d = 1; d < 32; d <<= 1) {
            int t = __shfl_up_sync(0xffffffffu, s, d);
            if (lane >= d) s += t;
        }
        if (lane == 31) wsum[wid] = s;
        __syncthreads();
        if (wid == 0) {
            int w = wsum[lane];
            #pragma unroll
            for (int d = 1; d < 32; d <<= 1) {
                int t = __shfl_up_sync(0xffffffffu, w, d);
                if (lane >= d) w += t;
            }
            wsum[lane] = w;
        }
        __syncthreads();
        int incl = s + (wid ? wsum[wid - 1] : 0) + running_sh;
        int excl = incl - v;
        if (i < n) { off[i] = excl; cur[i] = excl; }
        __syncthreads();
        if (tid == 1023) running_sh = incl;
        __syncthreads();
    }
}

__global__ void scatter_k(const int* __restrict__ src, const int* __restrict__ dst,
                          int ne, int* __restrict__ cur, int* __restrict__ esrc) {
    int i = blockIdx.x * blockDim.x + threadIdx.x;
    if (i < ne) {
        int p = atomicAdd(&cur[dst[i]], 1);
        esrc[p] = src[i];
    }
}

// ---------------- mean aggregation: one warp per destination node ----------
// Output is tf32-rounded (it always feeds a tf32 GEMM A operand).
template <int C>
__global__ void gather_mean_k(const float* __restrict__ x, const int* __restrict__ esrc,
                              const int* __restrict__ off, const int* __restrict__ cnt,
                              float* __restrict__ mean, int n_dst) {
    int warp = (blockIdx.x * blockDim.x + threadIdx.x) >> 5;
    int lane = threadIdx.x & 31;
    if (warp >= n_dst) return;
    int s = off[warp];
    int c = cnt[warp];
    constexpr int C4 = C / 4;
    constexpr int R = (C4 + 31) / 32;
    float4 acc[R];
    #pragma unroll
    for (int r = 0; r < R; r++) acc[r] = make_float4(0.f, 0.f, 0.f, 0.f);

    int e = 0;
    for (; e + 4 <= c; e += 4) {                     // 4-wide for MLP
        int r0 = esrc[s + e], r1 = esrc[s + e + 1];
        int r2 = esrc[s + e + 2], r3 = esrc[s + e + 3];
        const float4* p0 = (const float4*)(x + (size_t)r0 * C);
        const float4* p1 = (const float4*)(x + (size_t)r1 * C);
        const float4* p2 = (const float4*)(x + (size_t)r2 * C);
        const float4* p3 = (const float4*)(x + (size_t)r3 * C);
        #pragma unroll
        for (int r = 0; r < R; r++) {
            int f = lane + 32 * r;
            if (f < C4) {
                float4 v0 = __ldg(&p0[f]);
                float4 v1 = __ldg(&p1[f]);
                float4 v2 = __ldg(&p2[f]);
                float4 v3 = __ldg(&p3[f]);
                acc[r].x += v0.x + v1.x + v2.x + v3.x;
                acc[r].y += v0.y + v1.y + v2.y + v3.y;
                acc[r].z += v0.z + v1.z + v2.z + v3.z;
                acc[r].w += v0.w + v1.w + v2.w + v3.w;
            }
        }
    }
    for (; e < c; e++) {
        const float4* p = (const float4*)(x + (size_t)esrc[s + e] * C);
        #pragma unroll
        for (int r = 0; r < R; r++) {
            int f = lane + 32 * r;
            if (f < C4) {
                float4 v = __ldg(&p[f]);
                acc[r].x += v.x; acc[r].y += v.y; acc[r].z += v.z; acc[r].w += v.w;
            }
        }
    }
    float inv = 1.f / (float)(c > 1 ? c : 1);
    float4* mr = (float4*)(mean + (size_t)warp * C);
    #pragma unroll
    for (int r = 0; r < R; r++) {
        int f = lane + 32 * r;
        if (f < C4) {
            float4 v;
            v.x = rtf32(acc[r].x * inv); v.y = rtf32(acc[r].y * inv);
            v.z = rtf32(acc[r].z * inv); v.w = rtf32(acc[r].w * inv);
            mr[f] = v;
        }
    }
}

// ---------------- TF32 tensor-core dual GEMM (cp.async double-buffered) ----
// C[M,N] = A1[M,K] @ W1[N,K]^T + A2[M,K] @ W2[N,K]^T + bias ; optional relu,
// optional tf32-rounding of output (when it feeds the next layer's GEMM).
// All inputs must already be tf32-rounded fp32. M must be a multiple of 128.

#define TBM 128
#define TBN 128
#define TBK 32
#define TPAD 36
#define ABUF (2 * TBM * TPAD)
#define GEMM_SMEM (2 * (TBM + TBN) * TPAD * 4)

__device__ __forceinline__ void cp16(float* sdst, const float* gsrc, bool pred) {
    unsigned saddr = (unsigned)__cvta_generic_to_shared(sdst);
    int n = pred ? 16 : 0;
    asm volatile("cp.async.cg.shared.global [%0], [%1], 16, %2;\n"
                 :: "r"(saddr), "l"(gsrc), "r"(n));
}

__device__ __forceinline__ void mma_tf32(float* d, const unsigned* a, const unsigned* b) {
    asm volatile(
        "mma.sync.aligned.m16n8k8.row.col.f32.tf32.tf32.f32 "
        "{%0,%1,%2,%3}, {%4,%5,%6,%7}, {%8,%9}, {%0,%1,%2,%3};\n"
        : "+f"(d[0]), "+f"(d[1]), "+f"(d[2]), "+f"(d[3])
        : "r"(a[0]), "r"(a[1]), "r"(a[2]), "r"(a[3]), "r"(b[0]), "r"(b[1]));
}

__global__ __launch_bounds__(256) void gemm_dual_tf32_k(
    const float* __restrict__ A1, const float* __restrict__ W1,
    const float* __restrict__ A2, const float* __restrict__ W2,
    const float* __restrict__ bias, float* __restrict__ Cout,
    int M, int N, int K, int relu, int round_out) {
    extern __shared__ float smf[];
    #define SM_A(b, r, c) smf[(b) * (TBM * TPAD) + (r) * TPAD + (c)]
    #define SM_B(b, r, c) smf[ABUF + (b) * (TBN * TPAD) + (r) * TPAD + (c)]

    int tid = threadIdx.x;
    int lane = tid & 31;
    int wid = tid >> 5;
    int wm = wid & 3;
    int wn = wid >> 2;
    int g = lane >> 2;
    int tq = lane & 3;
    int blockM = blockIdx.y * TBM;
    int blockN = blockIdx.x * TBN;

    int ntk = (K + TBK - 1) / TBK;
    int T = 2 * ntk;

    float acc[2][8][4];
    #pragma unroll
    for (int mt = 0; mt < 2; mt++)
        #pragma unroll
        for (int nt = 0; nt < 8; nt++)
            #pragma unroll
            for (int q = 0; q < 4; q++) acc[mt][nt][q] = 0.f;

    auto load_tile = [&](int t, int buf) {
        int pass = (t >= ntk) ? 1 : 0;
        const float* A = pass ? A2 : A1;
        const float* W = pass ? W2 : W1;
        int k0 = (t - pass * ntk) * TBK;
        #pragma unroll
        for (int it = 0; it < 4; it++) {
            int s = tid + it * 256;
            int row = s >> 3, c4 = s & 7;
            int gk = k0 + c4 * 4;
            cp16(&SM_A(buf, row, c4 * 4), A + (size_t)(blockM + row) * K + gk,
                 gk + 4 <= K);
        }
        #pragma unroll
        for (int it = 0; it < 4; it++) {
            int s = tid + it * 256;
            int row = s >> 3, c4 = s & 7;
            int gk = k0 + c4 * 4;
            int gn = blockN + row;
            cp16(&SM_B(buf, row, c4 * 4), W + (size_t)gn * K + gk,
                 gn < N && gk + 4 <= K);
        }
    };

    load_tile(0, 0);
    asm volatile("cp.async.commit_group;\n");

    for (int t = 0; t < T; t++) {
        int buf = t & 1;
        if (t + 1 < T) {
            load_tile(t + 1, buf ^ 1);
            asm volatile("cp.async.commit_group;\n");
            asm volatile("cp.async.wait_group 1;\n");
        } else {
            asm volatile("cp.async.wait_group 0;\n");
        }
        __syncthreads();

        #pragma unroll
        for (int kk = 0; kk < TBK; kk += 8) {
            unsigned af[2][4], bf[8][2];
            #pragma unroll
            for (int mt = 0; mt < 2; mt++) {
                int r0 = wm * 32 + mt * 16;
                af[mt][0] = __float_as_uint(SM_A(buf, r0 + g, kk + tq));
                af[mt][1] = __float_as_uint(SM_A(buf, r0 + g + 8, kk + tq));
                af[mt][2] = __float_as_uint(SM_A(buf, r0 + g, kk + tq + 4));
                af[mt][3] = __float_as_uint(SM_A(buf, r0 + g + 8, kk + tq + 4));
            }
            #pragma unroll
            for (int nt = 0; nt < 8; nt++) {
                int c0 = wn * 64 + nt * 8;
                bf[nt][0] = __float_as_uint(SM_B(buf, c0 + g, kk + tq));
                bf[nt][1] = __float_as_uint(SM_B(buf, c0 + g, kk + tq + 4));
            }
            #pragma unroll
            for (int mt = 0; mt < 2; mt++)
                #pragma unroll
                for (int nt = 0; nt < 8; nt++)
                    mma_tf32(acc[mt][nt], af[mt], bf[nt]);
        }
        __syncthreads();
    }

    // epilogue
    #pragma unroll
    for (int mt = 0; mt < 2; mt++) {
        int r0 = blockM + wm * 32 + mt * 16 + g;
        #pragma unroll
        for (int nt = 0; nt < 8; nt++) {
            int c = blockN + wn * 64 + nt * 8 + 2 * tq;
            #pragma unroll
            for (int half = 0; half < 2; half++) {
                int rr = r0 + half * 8;
                #pragma unroll
                for (int j = 0; j < 2; j++) {
                    int cc = c + j;
                    if (cc < N) {
                        float v = acc[mt][nt][half * 2 + j] + __ldg(&bias[cc]);
                        if (relu) v = fmaxf(v, 0.f);
                        if (round_out) v = rtf32(v);
                        Cout[(size_t)rr * N + cc] = v;
                    }
                }
            }
        }
    }
    #undef SM_A
    #undef SM_B
}

// ---------------- log-softmax: one warp per row ----------------
__global__ void logsoftmax_k(const float* __restrict__ in, float* __restrict__ out,
                             int M, int N) {
    int row = blockIdx.x * (blockDim.x >> 5) + (threadIdx.x >> 5);
    int lane = threadIdx.x & 31;
    if (row >= M) return;
    const float* r = in + (size_t)row * N;
    float m = -1e30f;
    for (int c = lane; c < N; c += 32) m = fmaxf(m, r[c]);
    #pragma unroll
    for (int s = 16; s; s >>= 1) m = fmaxf(m, __shfl_xor_sync(0xffffffffu, m, s));
    float sum = 0.f;
    for (int c = lane; c < N; c += 32) sum += expf(r[c] - m);
    #pragma unroll
    for (int s = 16; s; s >>= 1) sum += __shfl_xor_sync(0xffffffffu, sum, s);
    float lse = logf(sum) + m;
    for (int c = lane; c < N; c += 32) out[(size_t)row * N + c] = r[c] - lse;
}

// ---------------- host driver ----------------
static void build_csr(const int* src, const int* dst, int ne, int nd,
                      int* cnt, int* off, int* cur, int* esrc) {
    zero_i_k<<<(nd + 255) / 256, 256>>>(cnt, nd);
    hist_k<<<(ne + 255) / 256, 256>>>(dst, ne, cnt);
    scan_k<<<1, 1024>>>(cnt, off, cur, nd);
    scatter_k<<<(ne + 255) / 256, 256>>>(src, dst, ne, cur, esrc);
}

extern "C" void kernel_launch(void* const* d_in, const int* in_sizes, int n_in,
                              void* d_out, int out_size) {
    const float* x    = (const float*)d_in[0];
    const int*   src0 = (const int*)d_in[1];
    const int*   dst0 = (const int*)d_in[2];
    const int*   src1 = (const int*)d_in[3];
    const int*   dst1 = (const int*)d_in[4];
    const int*   src2 = (const int*)d_in[5];
    const int*   dst2 = (const int*)d_in[6];
    const float* Wl0 = (const float*)d_in[7];
    const float* bl0 = (const float*)d_in[8];
    const float* Wr0 = (const float*)d_in[9];
    const float* Wl1 = (const float*)d_in[10];
    const float* bl1 = (const float*)d_in[11];
    const float* Wr1 = (const float*)d_in[12];
    const float* Wl2 = (const float*)d_in[13];
    const float* bl2 = (const float*)d_in[14];
    const float* Wr2 = (const float*)d_in[15];
    float* out = (float*)d_out;

    int *cnt, *off, *cur, *esrc;
    float *mean, *xr, *h1, *h2, *logits;
    cudaGetSymbolAddress((void**)&cnt, g_cnt);
    cudaGetSymbolAddress((void**)&off, g_off);
    cudaGetSymbolAddress((void**)&cur, g_cur);
    cudaGetSymbolAddress((void**)&esrc, g_esrc);
    cudaGetSymbolAddress((void**)&mean, g_mean);
    cudaGetSymbolAddress((void**)&xr, g_xr);
    cudaGetSymbolAddress((void**)&h1, g_h1);
    cudaGetSymbolAddress((void**)&h2, g_h2);
    cudaGetSymbolAddress((void**)&logits, g_logits);

    cudaFuncSetAttribute(gemm_dual_tf32_k,
                         cudaFuncAttributeMaxDynamicSharedMemorySize, GEMM_SMEM);

    // ---------- layer 0 : x[512000,100] -> h1[102400,256], relu ----------
    build_csr(src0, dst0, 1024000, 102400, cnt, off, cur, esrc);
    round_tf32_k<<<(102400 * 100 / 4 + 255) / 256, 256>>>(x, xr, 102400 * 100 / 4);
    gather_mean_k<100><<<(102400 * 32 + 255) / 256, 256>>>(x, esrc, off, cnt, mean, 102400);
    {
        dim3 g((256 + TBN - 1) / TBN, 102400 / TBM);
        gemm_dual_tf32_k<<<g, 256, GEMM_SMEM>>>(mean, Wl0, xr, Wr0, bl0, h1,
                                                102400, 256, 100, 1, 1);
    }

    // ---------- layer 1 : h1[102400,256] -> h2[10240,256], relu ----------
    build_csr(src1, dst1, 102400, 10240, cnt, off, cur, esrc);
    gather_mean_k<256><<<(10240 * 32 + 255) / 256, 256>>>(h1, esrc, off, cnt, mean, 10240);
    {
        dim3 g((256 + TBN - 1) / TBN, 10240 / TBM);
        gemm_dual_tf32_k<<<g, 256, GEMM_SMEM>>>(mean, Wl1, h1, Wr1, bl1, h2,
                                                10240, 256, 256, 1, 1);
    }

    // ---------- layer 2 : h2[10240,256] -> logits[1024,47] ----------
    build_csr(src2, dst2, 10240, 1024, cnt, off, cur, esrc);
    gather_mean_k<256><<<(1024 * 32 + 255) / 256, 256>>>(h2, esrc, off, cnt, mean, 1024);
    {
        dim3 g((47 + TBN - 1) / TBN, 1024 / TBM);
        gemm_dual_tf32_k<<<g, 256, GEMM_SMEM>>>(mean, Wl2, h2, Wr2, bl2, logits,
                                                1024, 47, 256, 0, 0);
    }

    // ---------- log_softmax ----------
    logsoftmax_k<<<(1024 + 7) / 8, 256>>>(logits, out, 1024, 47);
}

// round 9
// speedup vs baseline: 1.8245x; 1.0266x over previous
#include <cuda_runtime.h>
#include <cuda_bf16.h>
#include <math.h>
#include <stdint.h>

// ---------------- problem constants ----------------
// L0: 512000 -> 102400, E=1024000, 100 -> 256, relu
// L1: 102400 -> 10240,  E=102400,  256 -> 256, relu
// L2: 10240  -> 1024,   E=10240,   256 -> 47,  log_softmax

#define ND_MAX 102400
#define E_MAX  1024000

// ---------------- scratch ----------------
__device__ int   g_cnt[ND_MAX];
__device__ int   g_off[ND_MAX];
__device__ int   g_cur[ND_MAX];
__device__ int   g_esrc[E_MAX];
__device__ float g_mean[102400 * 100];
__device__ float g_h1[(size_t)102400 * 256];
__device__ float g_h2[10240 * 256];
__device__ float g_logits[1024 * 47];

__device__ __forceinline__ unsigned f2tf32(float f) {
    unsigned u;
    asm("cvt.rna.tf32.f32 %0, %1;" : "=r"(u) : "f"(f));
    return u;
}
__device__ __forceinline__ float rtf32(float f) { return __uint_as_float(f2tf32(f)); }

// ---------------- small utility kernels ----------------
__global__ void zero_i_k(int* p, int n) {
    int i = blockIdx.x * blockDim.x + threadIdx.x;
    if (i < n) p[i] = 0;
}

__global__ void hist_k(const int* __restrict__ dst, int ne, int* __restrict__ cnt) {
    int i = blockIdx.x * blockDim.x + threadIdx.x;
    if (i < ne) atomicAdd(&cnt[dst[i]], 1);
}

__global__ void scan_k(const int* __restrict__ cnt, int* __restrict__ off,
                       int* __restrict__ cur, int n) {
    __shared__ int wsum[32];
    __shared__ int running_sh;
    int tid = threadIdx.x;
    int lane = tid & 31, wid = tid >> 5;
    if (tid == 0) running_sh = 0;
    __syncthreads();
    for (int base = 0; base < n; base += 1024) {
        int i = base + tid;
        int v = (i < n) ? cnt[i] : 0;
        int s = v;
        #pragma unroll
        for (int d = 1; d < 32; d <<= 1) {
            int t = __shfl_up_sync(0xffffffffu, s, d);
            if (lane >= d) s += t;
        }
        if (lane == 31) wsum[wid] = s;
        __syncthreads();
        if (wid == 0) {
            int w = wsum[lane];
            #pragma unroll
            for (int d = 1; d < 32; d <<= 1) {
                int t = __shfl_up_sync(0xffffffffu, w, d);
                if (lane >= d) w += t;
            }
            wsum[lane] = w;
        }
        __syncthreads();
        int incl = s + (wid ? wsum[wid - 1] : 0) + running_sh;
        int excl = incl - v;
        if (i < n) { off[i] = excl; cur[i] = excl; }
        __syncthreads();
        if (tid == 1023) running_sh = incl;
        __syncthreads();
    }
}

__global__ void scatter_k(const int* __restrict__ src, const int* __restrict__ dst,
                          int ne, int* __restrict__ cur, int* __restrict__ esrc) {
    int i = blockIdx.x * blockDim.x + threadIdx.x;
    if (i < ne) {
        int p = atomicAdd(&cur[dst[i]], 1);
        esrc[p] = src[i];
    }
}

// ---------------- mean aggregation: one warp per destination node ----------
template <int C>
__global__ void gather_mean_k(const float* __restrict__ x, const int* __restrict__ esrc,
                              const int* __restrict__ off, const int* __restrict__ cnt,
                              float* __restrict__ mean, int n_dst) {
    int warp = (blockIdx.x * blockDim.x + threadIdx.x) >> 5;
    int lane = threadIdx.x & 31;
    if (warp >= n_dst) return;
    int s = off[warp];
    int c = cnt[warp];
    constexpr int C4 = C / 4;
    constexpr int R = (C4 + 31) / 32;
    float4 acc[R];
    #pragma unroll
    for (int r = 0; r < R; r++) acc[r] = make_float4(0.f, 0.f, 0.f, 0.f);

    int e = 0;
    for (; e + 4 <= c; e += 4) {
        int r0 = esrc[s + e], r1 = esrc[s + e + 1];
        int r2 = esrc[s + e + 2], r3 = esrc[s + e + 3];
        const float4* p0 = (const float4*)(x + (size_t)r0 * C);
        const float4* p1 = (const float4*)(x + (size_t)r1 * C);
        const float4* p2 = (const float4*)(x + (size_t)r2 * C);
        const float4* p3 = (const float4*)(x + (size_t)r3 * C);
        #pragma unroll
        for (int r = 0; r < R; r++) {
            int f = lane + 32 * r;
            if (f < C4) {
                float4 v0 = __ldg(&p0[f]);
                float4 v1 = __ldg(&p1[f]);
                float4 v2 = __ldg(&p2[f]);
                float4 v3 = __ldg(&p3[f]);
                acc[r].x += v0.x + v1.x + v2.x + v3.x;
                acc[r].y += v0.y + v1.y + v2.y + v3.y;
                acc[r].z += v0.z + v1.z + v2.z + v3.z;
                acc[r].w += v0.w + v1.w + v2.w + v3.w;
            }
        }
    }
    for (; e < c; e++) {
        const float4* p = (const float4*)(x + (size_t)esrc[s + e] * C);
        #pragma unroll
        for (int r = 0; r < R; r++) {
            int f = lane + 32 * r;
            if (f < C4) {
                float4 v = __ldg(&p[f]);
                acc[r].x += v.x; acc[r].y += v.y; acc[r].z += v.z; acc[r].w += v.w;
            }
        }
    }
    float inv = 1.f / (float)(c > 1 ? c : 1);
    float4* mr = (float4*)(mean + (size_t)warp * C);
    #pragma unroll
    for (int r = 0; r < R; r++) {
        int f = lane + 32 * r;
        if (f < C4) {
            float4 v;
            v.x = rtf32(acc[r].x * inv); v.y = rtf32(acc[r].y * inv);
            v.z = rtf32(acc[r].z * inv); v.w = rtf32(acc[r].w * inv);
            mr[f] = v;
        }
    }
}

// ---------------- TF32 mma.sync dual GEMM (cp.async double-buffered) -------
// C[M,N] = A1[M,K] @ W1[N,K]^T + A2[M,K] @ W2[N,K]^T + bias ; optional relu,
// optional tf32-rounding of output. fp32 inputs; HW truncates low mantissa.
#define TBM 128
#define TBN 128
#define TBK 32
#define TPAD 36
#define ABUF (2 * TBM * TPAD)
#define GEMM_SMEM (2 * (TBM + TBN) * TPAD * 4)

__device__ __forceinline__ void cp16(float* sdst, const float* gsrc, bool pred) {
    unsigned saddr = (unsigned)__cvta_generic_to_shared(sdst);
    int n = pred ? 16 : 0;
    asm volatile("cp.async.cg.shared.global [%0], [%1], 16, %2;\n"
                 :: "r"(saddr), "l"(gsrc), "r"(n));
}

__device__ __forceinline__ void mma_tf32(float* d, const unsigned* a, const unsigned* b) {
    asm volatile(
        "mma.sync.aligned.m16n8k8.row.col.f32.tf32.tf32.f32 "
        "{%0,%1,%2,%3}, {%4,%5,%6,%7}, {%8,%9}, {%0,%1,%2,%3};\n"
        : "+f"(d[0]), "+f"(d[1]), "+f"(d[2]), "+f"(d[3])
        : "r"(a[0]), "r"(a[1]), "r"(a[2]), "r"(a[3]), "r"(b[0]), "r"(b[1]));
}

__global__ __launch_bounds__(256) void gemm_dual_tf32_k(
    const float* __restrict__ A1, const float* __restrict__ W1,
    const float* __restrict__ A2, const float* __restrict__ W2,
    const float* __restrict__ bias, float* __restrict__ Cout,
    int M, int N, int K, int relu, int round_out) {
    extern __shared__ float smf[];
    #define SM_A(b, r, c) smf[(b) * (TBM * TPAD) + (r) * TPAD + (c)]
    #define SM_B(b, r, c) smf[ABUF + (b) * (TBN * TPAD) + (r) * TPAD + (c)]

    int tid = threadIdx.x;
    int lane = tid & 31;
    int wid = tid >> 5;
    int wm = wid & 3;
    int wn = wid >> 2;
    int g = lane >> 2;
    int tq = lane & 3;
    int blockM = blockIdx.y * TBM;
    int blockN = blockIdx.x * TBN;

    int ntk = (K + TBK - 1) / TBK;
    int T = 2 * ntk;

    float acc[2][8][4];
    #pragma unroll
    for (int mt = 0; mt < 2; mt++)
        #pragma unroll
        for (int nt = 0; nt < 8; nt++)
            #pragma unroll
            for (int q = 0; q < 4; q++) acc[mt][nt][q] = 0.f;

    auto load_tile = [&](int t, int buf) {
        int pass = (t >= ntk) ? 1 : 0;
        const float* A = pass ? A2 : A1;
        const float* W = pass ? W2 : W1;
        int k0 = (t - pass * ntk) * TBK;
        #pragma unroll
        for (int it = 0; it < 4; it++) {
            int s = tid + it * 256;
            int row = s >> 3, c4 = s & 7;
            int gk = k0 + c4 * 4;
            cp16(&SM_A(buf, row, c4 * 4), A + (size_t)(blockM + row) * K + gk,
                 gk + 4 <= K);
        }
        #pragma unroll
        for (int it = 0; it < 4; it++) {
            int s = tid + it * 256;
            int row = s >> 3, c4 = s & 7;
            int gk = k0 + c4 * 4;
            int gn = blockN + row;
            cp16(&SM_B(buf, row, c4 * 4), W + (size_t)gn * K + gk,
                 gn < N && gk + 4 <= K);
        }
    };

    load_tile(0, 0);
    asm volatile("cp.async.commit_group;\n");

    for (int t = 0; t < T; t++) {
        int buf = t & 1;
        if (t + 1 < T) {
            load_tile(t + 1, buf ^ 1);
            asm volatile("cp.async.commit_group;\n");
            asm volatile("cp.async.wait_group 1;\n");
        } else {
            asm volatile("cp.async.wait_group 0;\n");
        }
        __syncthreads();

        #pragma unroll
        for (int kk = 0; kk < TBK; kk += 8) {
            unsigned af[2][4], bf[8][2];
            #pragma unroll
            for (int mt = 0; mt < 2; mt++) {
                int r0 = wm * 32 + mt * 16;
                af[mt][0] = __float_as_uint(SM_A(buf, r0 + g, kk + tq));
                af[mt][1] = __float_as_uint(SM_A(buf, r0 + g + 8, kk + tq));
                af[mt][2] = __float_as_uint(SM_A(buf, r0 + g, kk + tq + 4));
                af[mt][3] = __float_as_uint(SM_A(buf, r0 + g + 8, kk + tq + 4));
            }
            #pragma unroll
            for (int nt = 0; nt < 8; nt++) {
                int c0 = wn * 64 + nt * 8;
                bf[nt][0] = __float_as_uint(SM_B(buf, c0 + g, kk + tq));
                bf[nt][1] = __float_as_uint(SM_B(buf, c0 + g, kk + tq + 4));
            }
            #pragma unroll
            for (int mt = 0; mt < 2; mt++)
                #pragma unroll
                for (int nt = 0; nt < 8; nt++)
                    mma_tf32(acc[mt][nt], af[mt], bf[nt]);
        }
        __syncthreads();
    }

    #pragma unroll
    for (int mt = 0; mt < 2; mt++) {
        int r0 = blockM + wm * 32 + mt * 16 + g;
        #pragma unroll
        for (int nt = 0; nt < 8; nt++) {
            int c = blockN + wn * 64 + nt * 8 + 2 * tq;
            #pragma unroll
            for (int half = 0; half < 2; half++) {
                int rr = r0 + half * 8;
                #pragma unroll
                for (int j = 0; j < 2; j++) {
                    int cc = c + j;
                    if (cc < N) {
                        float v = acc[mt][nt][half * 2 + j] + __ldg(&bias[cc]);
                        if (relu) v = fmaxf(v, 0.f);
                        if (round_out) v = rtf32(v);
                        Cout[(size_t)rr * N + cc] = v;
                    }
                }
            }
        }
    }
    #undef SM_A
    #undef SM_B
}

// ---------------- log-softmax ----------------
__global__ void logsoftmax_k(const float* __restrict__ in, float* __restrict__ out,
                             int M, int N) {
    int row = blockIdx.x * (blockDim.x >> 5) + (threadIdx.x >> 5);
    int lane = threadIdx.x & 31;
    if (row >= M) return;
    const float* r = in + (size_t)row * N;
    float m = -1e30f;
    for (int c = lane; c < N; c += 32) m = fmaxf(m, r[c]);
    #pragma unroll
    for (int s = 16; s; s >>= 1) m = fmaxf(m, __shfl_xor_sync(0xffffffffu, m, s));
    float sum = 0.f;
    for (int c = lane; c < N; c += 32) sum += expf(r[c] - m);
    #pragma unroll
    for (int s = 16; s; s >>= 1) sum += __shfl_xor_sync(0xffffffffu, sum, s);
    float lse = logf(sum) + m;
    for (int c = lane; c < N; c += 32) out[(size_t)row * N + c] = r[c] - lse;
}

// ---------------- host driver ----------------
static void build_csr(const int* src, const int* dst, int ne, int nd,
                      int* cnt, int* off, int* cur, int* esrc) {
    zero_i_k<<<(nd + 255) / 256, 256>>>(cnt, nd);
    hist_k<<<(ne + 255) / 256, 256>>>(dst, ne, cnt);
    scan_k<<<1, 1024>>>(cnt, off, cur, nd);
    scatter_k<<<(ne + 255) / 256, 256>>>(src, dst, ne, cur, esrc);
}

extern "C" void kernel_launch(void* const* d_in, const int* in_sizes, int n_in,
                              void* d_out, int out_size) {
    const float* x    = (const float*)d_in[0];
    const int*   src0 = (const int*)d_in[1];
    const int*   dst0 = (const int*)d_in[2];
    const int*   src1 = (const int*)d_in[3];
    const int*   dst1 = (const int*)d_in[4];
    const int*   src2 = (const int*)d_in[5];
    const int*   dst2 = (const int*)d_in[6];
    const float* Wl0 = (const float*)d_in[7];
    const float* bl0 = (const float*)d_in[8];
    const float* Wr0 = (const float*)d_in[9];
    const float* Wl1 = (const float*)d_in[10];
    const float* bl1 = (const float*)d_in[11];
    const float* Wr1 = (const float*)d_in[12];
    const float* Wl2 = (const float*)d_in[13];
    const float* bl2 = (const float*)d_in[14];
    const float* Wr2 = (const float*)d_in[15];
    float* out = (float*)d_out;

    int *cnt, *off, *cur, *esrc;
    float *mean, *h1, *h2, *logits;
    cudaGetSymbolAddress((void**)&cnt, g_cnt);
    cudaGetSymbolAddress((void**)&off, g_off);
    cudaGetSymbolAddress((void**)&cur, g_cur);
    cudaGetSymbolAddress((void**)&esrc, g_esrc);
    cudaGetSymbolAddress((void**)&mean, g_mean);
    cudaGetSymbolAddress((void**)&h1, g_h1);
    cudaGetSymbolAddress((void**)&h2, g_h2);
    cudaGetSymbolAddress((void**)&logits, g_logits);

    cudaFuncSetAttribute(gemm_dual_tf32_k,
                         cudaFuncAttributeMaxDynamicSharedMemorySize, GEMM_SMEM);

    // ---------- layer 0 : x[512000,100] -> h1[102400,256], relu ----------
    build_csr(src0, dst0, 1024000, 102400, cnt, off, cur, esrc);
    gather_mean_k<100><<<(102400 * 32 + 255) / 256, 256>>>(x, esrc, off, cnt, mean, 102400);
    {
        dim3 g((256 + TBN - 1) / TBN, 102400 / TBM);
        gemm_dual_tf32_k<<<g, 256, GEMM_SMEM>>>(mean, Wl0, x, Wr0, bl0, h1,
                                                102400, 256, 100, 1, 1);
    }

    // ---------- layer 1 : h1[102400,256] -> h2[10240,256], relu ----------
    build_csr(src1, dst1, 102400, 10240, cnt, off, cur, esrc);
    gather_mean_k<256><<<(10240 * 32 + 255) / 256, 256>>>(h1, esrc, off, cnt, mean, 10240);
    {
        dim3 g((256 + TBN - 1) / TBN, 10240 / TBM);
        gemm_dual_tf32_k<<<g, 256, GEMM_SMEM>>>(mean, Wl1, h1, Wr1, bl1, h2,
                                                10240, 256, 256, 1, 1);
    }

    // ---------- layer 2 : h2[10240,256] -> logits[1024,47] ----------
    build_csr(src2, dst2, 10240, 1024, cnt, off, cur, esrc);
    gather_mean_k<256><<<(1024 * 32 + 255) / 256, 256>>>(h2, esrc, off, cnt, mean, 1024);
    {
        dim3 g((47 + TBN - 1) / TBN, 1024 / TBM);
        gemm_dual_tf32_k<<<g, 256, GEMM_SMEM>>>(mean, Wl2, h2, Wr2, bl2, logits,
                                                1024, 47, 256, 0, 0);
    }

    // ---------- log_softmax ----------
    logsoftmax_k<<<(1024 + 7) / 8, 256>>>(logits, out, 1024, 47);
}